// round 1
// baseline (speedup 1.0000x reference)
#include <cuda_runtime.h>
#include <math.h>

#define Nn 4096
#define Mm 4096
#define Dd 1024
#define NITER 200

// Static device scratch (allowed; no runtime allocation).
static __device__ float g_xn[(size_t)Nn * Dd];
static __device__ float g_yn[(size_t)Mm * Dd];
static __device__ float g_A[(size_t)Nn * Mm];
static __device__ float g_K[(size_t)Nn * Mm];
static __device__ float g_u[Nn];
static __device__ float g_v[Mm];

// ---------------------------------------------------------------------------
// Row L2-normalization: one block per row, 256 threads, Dd=1024 -> 1 float4/thread
// ---------------------------------------------------------------------------
__global__ void __launch_bounds__(256) normalize_rows(const float* __restrict__ in, int which) {
    int row = blockIdx.x;
    const float4* src = (const float4*)(in + (size_t)row * Dd);
    float4 val = src[threadIdx.x];
    float ss = val.x * val.x + val.y * val.y + val.z * val.z + val.w * val.w;
#pragma unroll
    for (int o = 16; o; o >>= 1) ss += __shfl_xor_sync(0xffffffffu, ss, o);
    __shared__ float wsum[8];
    int lane = threadIdx.x & 31, warp = threadIdx.x >> 5;
    if (!lane) wsum[warp] = ss;
    __syncthreads();
    float tot = 0.f;
#pragma unroll
    for (int p = 0; p < 8; p++) tot += wsum[p];
    float inv = rsqrtf(tot);
    float* dst = (which ? g_yn : g_xn) + (size_t)row * Dd;
    ((float4*)dst)[threadIdx.x] =
        make_float4(val.x * inv, val.y * inv, val.z * inv, val.w * inv);
}

// ---------------------------------------------------------------------------
// GEMM1 (NT): A[i][j] = dot(xn[i,:], yn[j,:]); epilogue K = exp(A)
// 128x128 tile, BK=16, 256 threads, 8x8 per thread.
// ---------------------------------------------------------------------------
__global__ void __launch_bounds__(256) gemm_nt_exp() {
    __shared__ float Xs[16][128 + 4];
    __shared__ float Ys[16][128 + 4];
    int bi = blockIdx.y, bj = blockIdx.x;
    int tid = threadIdx.x;
    int tx = tid & 15, ty = tid >> 4;

    float acc[8][8];
#pragma unroll
    for (int i = 0; i < 8; i++)
#pragma unroll
        for (int j = 0; j < 8; j++) acc[i][j] = 0.f;

    const float* Xg = g_xn + (size_t)(bi * 128) * Dd;
    const float* Yg = g_yn + (size_t)(bj * 128) * Dd;
    int lr = tid >> 2;          // 0..63
    int lc = (tid & 3) * 4;     // 0,4,8,12

    for (int k0 = 0; k0 < Dd; k0 += 16) {
#pragma unroll
        for (int p = 0; p < 2; p++) {
            int r = lr + p * 64;
            float4 xv = *(const float4*)(Xg + (size_t)r * Dd + k0 + lc);
            float4 yv = *(const float4*)(Yg + (size_t)r * Dd + k0 + lc);
            Xs[lc + 0][r] = xv.x; Xs[lc + 1][r] = xv.y;
            Xs[lc + 2][r] = xv.z; Xs[lc + 3][r] = xv.w;
            Ys[lc + 0][r] = yv.x; Ys[lc + 1][r] = yv.y;
            Ys[lc + 2][r] = yv.z; Ys[lc + 3][r] = yv.w;
        }
        __syncthreads();
#pragma unroll
        for (int kk = 0; kk < 16; kk++) {
            float a[8], b[8];
            *(float4*)&a[0] = *(float4*)&Xs[kk][ty * 8];
            *(float4*)&a[4] = *(float4*)&Xs[kk][ty * 8 + 4];
            *(float4*)&b[0] = *(float4*)&Ys[kk][tx * 8];
            *(float4*)&b[4] = *(float4*)&Ys[kk][tx * 8 + 4];
#pragma unroll
            for (int i = 0; i < 8; i++)
#pragma unroll
                for (int j = 0; j < 8; j++)
                    acc[i][j] = fmaf(a[i], b[j], acc[i][j]);
        }
        __syncthreads();
    }

#pragma unroll
    for (int i = 0; i < 8; i++) {
        int row = bi * 128 + ty * 8 + i;
        size_t base = (size_t)row * Mm + bj * 128 + tx * 8;
#pragma unroll
        for (int q = 0; q < 2; q++) {
            float4 av = make_float4(acc[i][q * 4 + 0], acc[i][q * 4 + 1],
                                    acc[i][q * 4 + 2], acc[i][q * 4 + 3]);
            *(float4*)&g_A[base + q * 4] = av;
            float4 kv = make_float4(expf(av.x), expf(av.y), expf(av.z), expf(av.w));
            *(float4*)&g_K[base + q * 4] = kv;
        }
    }
}

// ---------------------------------------------------------------------------
// Sinkhorn
// ---------------------------------------------------------------------------
__global__ void init_uv() {
    int i = blockIdx.x * 256 + threadIdx.x;
    g_u[i] = 1.0f / Nn;
    g_v[i] = 1.0f / Mm;
}

// u[i] = sqrt(a / (K v)[i]).  One warp per row, 8 rows per block, grid 512.
__global__ void __launch_bounds__(256) rowpass() {
    int warp = threadIdx.x >> 5, lane = threadIdx.x & 31;
    int row = (blockIdx.x << 3) + warp;
    const float4* Kr = (const float4*)(g_K + (size_t)row * Mm);
    const float4* v4 = (const float4*)g_v;
    float acc = 0.f;
#pragma unroll 8
    for (int j = lane; j < Mm / 4; j += 32) {
        float4 k = Kr[j], vv = v4[j];
        acc += k.x * vv.x + k.y * vv.y + k.z * vv.z + k.w * vv.w;
    }
#pragma unroll
    for (int o = 16; o; o >>= 1) acc += __shfl_xor_sync(0xffffffffu, acc, o);
    if (!lane) g_u[row] = sqrtf((1.0f / Nn) / acc);
}

// v[j] = sqrt(b / (K^T u)[j]).  32 cols per block, 8 row-groups, grid 128.
__global__ void __launch_bounds__(256) colpass() {
    __shared__ float part[8][33];
    int c = threadIdx.x & 31, g = threadIdx.x >> 5;
    int j = (blockIdx.x << 5) + c;
    float acc = 0.f;
#pragma unroll 4
    for (int r = g; r < Nn; r += 8) {
        acc += g_K[(size_t)r * Mm + j] * g_u[r];
    }
    part[g][c] = acc;
    __syncthreads();
    if (g == 0) {
        float s = part[0][c];
#pragma unroll
        for (int p = 1; p < 8; p++) s += part[p][c];
        g_v[j] = sqrtf((1.0f / Mm) / s);
    }
}

// ---------------------------------------------------------------------------
// T = A * (u K v), written directly into d_out's T region.
// ---------------------------------------------------------------------------
__global__ void __launch_bounds__(256) finalize_T(float* __restrict__ T) {
    int row = blockIdx.x;
    float u = g_u[row];
    size_t base = (size_t)row * Mm;
    const float4* A4 = (const float4*)(g_A + base);
    const float4* K4 = (const float4*)(g_K + base);
    const float4* v4 = (const float4*)g_v;
    float4* T4 = (float4*)(T + base);
    for (int q = threadIdx.x; q < Mm / 4; q += 256) {
        float4 a = A4[q], k = K4[q], vv = v4[q];
        T4[q] = make_float4(a.x * u * k.x * vv.x,
                            a.y * u * k.y * vv.y,
                            a.z * u * k.z * vv.z,
                            a.w * u * k.w * vv.w);
    }
}

// ---------------------------------------------------------------------------
// GEMM2 (TN): C[j][k] = sum_i T[i][j] * X[i][k]   (aligned = T^T @ source)
// ---------------------------------------------------------------------------
__global__ void __launch_bounds__(256) gemm_tn(const float* __restrict__ T,
                                               const float* __restrict__ X,
                                               float* __restrict__ C) {
    __shared__ float Ts[16][128 + 4];
    __shared__ float Xs[16][128 + 4];
    int bj = blockIdx.y;   // tile over M (rows of C)
    int bk = blockIdx.x;   // tile over D (cols of C)
    int tid = threadIdx.x;
    int tx = tid & 15, ty = tid >> 4;

    float acc[8][8];
#pragma unroll
    for (int i = 0; i < 8; i++)
#pragma unroll
        for (int j = 0; j < 8; j++) acc[i][j] = 0.f;

    int lr = tid >> 5;          // 0..7
    int lc = (tid & 31) * 4;    // 0..124

    for (int i0 = 0; i0 < Nn; i0 += 16) {
#pragma unroll
        for (int p = 0; p < 2; p++) {
            int r = lr + p * 8;
            float4 tv = *(const float4*)(T + (size_t)(i0 + r) * Mm + bj * 128 + lc);
            float4 xv = *(const float4*)(X + (size_t)(i0 + r) * Dd + bk * 128 + lc);
            *(float4*)&Ts[r][lc] = tv;
            *(float4*)&Xs[r][lc] = xv;
        }
        __syncthreads();
#pragma unroll
        for (int kk = 0; kk < 16; kk++) {
            float a[8], b[8];
            *(float4*)&a[0] = *(float4*)&Ts[kk][ty * 8];
            *(float4*)&a[4] = *(float4*)&Ts[kk][ty * 8 + 4];
            *(float4*)&b[0] = *(float4*)&Xs[kk][tx * 8];
            *(float4*)&b[4] = *(float4*)&Xs[kk][tx * 8 + 4];
#pragma unroll
            for (int i = 0; i < 8; i++)
#pragma unroll
                for (int j = 0; j < 8; j++)
                    acc[i][j] = fmaf(a[i], b[j], acc[i][j]);
        }
        __syncthreads();
    }

#pragma unroll
    for (int i = 0; i < 8; i++) {
        int row = bj * 128 + ty * 8 + i;
        size_t base = (size_t)row * Dd + bk * 128 + tx * 8;
#pragma unroll
        for (int q = 0; q < 2; q++) {
            *(float4*)&C[base + q * 4] =
                make_float4(acc[i][q * 4 + 0], acc[i][q * 4 + 1],
                            acc[i][q * 4 + 2], acc[i][q * 4 + 3]);
        }
    }
}

// ---------------------------------------------------------------------------
extern "C" void kernel_launch(void* const* d_in, const int* in_sizes, int n_in,
                              void* d_out, int out_size) {
    const float* X = (const float*)d_in[0];   // source [4096,1024]
    const float* Y = (const float*)d_in[1];   // target [4096,1024]
    float* out = (float*)d_out;
    float* aligned = out;                          // [4096,1024]
    float* Tmat = out + (size_t)Mm * Dd;           // [4096,4096]

    normalize_rows<<<Nn, 256>>>(X, 0);
    normalize_rows<<<Mm, 256>>>(Y, 1);

    dim3 g1(Mm / 128, Nn / 128);
    gemm_nt_exp<<<g1, 256>>>();

    init_uv<<<Nn / 256, 256>>>();
    for (int it = 0; it < NITER; it++) {
        rowpass<<<Nn / 8, 256>>>();
        colpass<<<Mm / 32, 256>>>();
    }

    finalize_T<<<Nn, 256>>>(Tmat);

    dim3 g2(Dd / 128, Mm / 128);
    gemm_tn<<<g2, 256>>>(Tmat, X, aligned);
}

// round 2
// speedup vs baseline: 3.4747x; 3.4747x over previous
#include <cuda_runtime.h>
#include <cuda_bf16.h>
#include <math.h>

#define Nn 4096
#define Mm 4096
#define Dd 1024
#define NITER 40

// Static device scratch (no runtime allocation allowed).
static __device__ float g_xn[(size_t)Nn * Dd];
static __device__ float g_yn[(size_t)Mm * Dd];
static __device__ float g_A[(size_t)Nn * Mm];
static __device__ __nv_bfloat16 g_K16[(size_t)Nn * Mm];
static __device__ float g_u[Nn];
static __device__ float g_v[Mm];

// ---------------------------------------------------------------------------
// Row L2-normalization
// ---------------------------------------------------------------------------
__global__ void __launch_bounds__(256) normalize_rows(const float* __restrict__ in, int which) {
    int row = blockIdx.x;
    const float4* src = (const float4*)(in + (size_t)row * Dd);
    float4 val = src[threadIdx.x];
    float ss = val.x * val.x + val.y * val.y + val.z * val.z + val.w * val.w;
#pragma unroll
    for (int o = 16; o; o >>= 1) ss += __shfl_xor_sync(0xffffffffu, ss, o);
    __shared__ float wsum[8];
    int lane = threadIdx.x & 31, warp = threadIdx.x >> 5;
    if (!lane) wsum[warp] = ss;
    __syncthreads();
    float tot = 0.f;
#pragma unroll
    for (int p = 0; p < 8; p++) tot += wsum[p];
    float inv = rsqrtf(tot);
    float* dst = (which ? g_yn : g_xn) + (size_t)row * Dd;
    ((float4*)dst)[threadIdx.x] =
        make_float4(val.x * inv, val.y * inv, val.z * inv, val.w * inv);
}

// ---------------------------------------------------------------------------
// GEMM1 (NT), double-buffered: A[i][j] = dot(xn[i,:], yn[j,:]);
// epilogue writes A (fp32) and K16 = bf16(exp(A)).
// 128x128 tile, BK=16, 256 threads, 8x8/thread in 4+4 quadrant layout.
// ---------------------------------------------------------------------------
__global__ void __launch_bounds__(256, 2) gemm_nt_exp() {
    __shared__ float Xs[2][16][128];
    __shared__ float Ys[2][16][128];
    int bi = blockIdx.y, bj = blockIdx.x;
    int tid = threadIdx.x;
    int tx = tid & 15, ty = tid >> 4;
    int lr = tid >> 2;          // 0..63
    int lc = (tid & 3) * 4;     // 0,4,8,12

    const float* Xg = g_xn + (size_t)(bi * 128) * Dd;
    const float* Yg = g_yn + (size_t)(bj * 128) * Dd;

    float acc[8][8];
#pragma unroll
    for (int i = 0; i < 8; i++)
#pragma unroll
        for (int j = 0; j < 8; j++) acc[i][j] = 0.f;

    float4 rx[2], ry[2];
    // prologue: tile 0
#pragma unroll
    for (int q = 0; q < 2; q++) {
        int r = lr + q * 64;
        rx[q] = *(const float4*)(Xg + (size_t)r * Dd + lc);
        ry[q] = *(const float4*)(Yg + (size_t)r * Dd + lc);
    }
#pragma unroll
    for (int q = 0; q < 2; q++) {
        int r = lr + q * 64;
        Xs[0][lc + 0][r] = rx[q].x; Xs[0][lc + 1][r] = rx[q].y;
        Xs[0][lc + 2][r] = rx[q].z; Xs[0][lc + 3][r] = rx[q].w;
        Ys[0][lc + 0][r] = ry[q].x; Ys[0][lc + 1][r] = ry[q].y;
        Ys[0][lc + 2][r] = ry[q].z; Ys[0][lc + 3][r] = ry[q].w;
    }
    __syncthreads();

    const int NT = Dd / 16;
    for (int kt = 0; kt < NT; kt++) {
        int buf = kt & 1;
        if (kt + 1 < NT) {
            int k0 = (kt + 1) * 16;
#pragma unroll
            for (int q = 0; q < 2; q++) {
                int r = lr + q * 64;
                rx[q] = *(const float4*)(Xg + (size_t)r * Dd + k0 + lc);
                ry[q] = *(const float4*)(Yg + (size_t)r * Dd + k0 + lc);
            }
        }
#pragma unroll
        for (int kk = 0; kk < 16; kk++) {
            float a[8], b[8];
            *(float4*)&a[0] = *(const float4*)&Xs[buf][kk][ty * 4];
            *(float4*)&a[4] = *(const float4*)&Xs[buf][kk][64 + ty * 4];
            *(float4*)&b[0] = *(const float4*)&Ys[buf][kk][tx * 4];
            *(float4*)&b[4] = *(const float4*)&Ys[buf][kk][64 + tx * 4];
#pragma unroll
            for (int i = 0; i < 8; i++)
#pragma unroll
                for (int j = 0; j < 8; j++)
                    acc[i][j] = fmaf(a[i], b[j], acc[i][j]);
        }
        if (kt + 1 < NT) {
            int nb = 1 - buf;
#pragma unroll
            for (int q = 0; q < 2; q++) {
                int r = lr + q * 64;
                Xs[nb][lc + 0][r] = rx[q].x; Xs[nb][lc + 1][r] = rx[q].y;
                Xs[nb][lc + 2][r] = rx[q].z; Xs[nb][lc + 3][r] = rx[q].w;
                Ys[nb][lc + 0][r] = ry[q].x; Ys[nb][lc + 1][r] = ry[q].y;
                Ys[nb][lc + 2][r] = ry[q].z; Ys[nb][lc + 3][r] = ry[q].w;
            }
            __syncthreads();
        }
    }

#pragma unroll
    for (int ih = 0; ih < 2; ih++)
#pragma unroll
    for (int i = 0; i < 4; i++) {
        int row = bi * 128 + ih * 64 + ty * 4 + i;
        size_t base = (size_t)row * Mm + bj * 128;
#pragma unroll
        for (int jh = 0; jh < 2; jh++) {
            int col = jh * 64 + tx * 4;
            float4 av = make_float4(acc[ih * 4 + i][jh * 4 + 0],
                                    acc[ih * 4 + i][jh * 4 + 1],
                                    acc[ih * 4 + i][jh * 4 + 2],
                                    acc[ih * 4 + i][jh * 4 + 3]);
            *(float4*)&g_A[base + col] = av;
            __nv_bfloat162 k01 = __floats2bfloat162_rn(expf(av.x), expf(av.y));
            __nv_bfloat162 k23 = __floats2bfloat162_rn(expf(av.z), expf(av.w));
            uint2 pk;
            pk.x = *(unsigned*)&k01;
            pk.y = *(unsigned*)&k23;
            *(uint2*)&g_K16[base + col] = pk;
        }
    }
}

// ---------------------------------------------------------------------------
// Sinkhorn (bf16 K, fp32 accumulate)
// ---------------------------------------------------------------------------
__global__ void init_uv() {
    int i = blockIdx.x * 256 + threadIdx.x;
    g_u[i] = 1.0f / Nn;
    g_v[i] = 1.0f / Mm;
}

// u[i] = sqrt(a / (K v)[i]).  One warp per row; grid 512 x 256thr.
__global__ void __launch_bounds__(256) rowpass() {
    int warp = threadIdx.x >> 5, lane = threadIdx.x & 31;
    int row = (blockIdx.x << 3) + warp;
    const uint4* Kr = (const uint4*)(g_K16 + (size_t)row * Mm);  // 8 bf16 per uint4
    const float4* v4 = (const float4*)g_v;
    float acc = 0.f;
#pragma unroll 4
    for (int j = lane; j < Mm / 8; j += 32) {
        uint4 kq = Kr[j];
        float4 va = v4[2 * j], vb = v4[2 * j + 1];
        float2 k0 = __bfloat1622float2(*(__nv_bfloat162*)&kq.x);
        float2 k1 = __bfloat1622float2(*(__nv_bfloat162*)&kq.y);
        float2 k2 = __bfloat1622float2(*(__nv_bfloat162*)&kq.z);
        float2 k3 = __bfloat1622float2(*(__nv_bfloat162*)&kq.w);
        acc += k0.x * va.x + k0.y * va.y + k1.x * va.z + k1.y * va.w
             + k2.x * vb.x + k2.y * vb.y + k3.x * vb.z + k3.y * vb.w;
    }
#pragma unroll
    for (int o = 16; o; o >>= 1) acc += __shfl_xor_sync(0xffffffffu, acc, o);
    if (!lane) g_u[row] = sqrtf((1.0f / Nn) / acc);
}

// v[j] = sqrt(b / (K^T u)[j]).  64 cols/block (bf16x2 per lane), grid 64.
__global__ void __launch_bounds__(256) colpass() {
    __shared__ float us[Nn];        // 16 KB
    __shared__ float part[8][66];
    for (int i = threadIdx.x; i < Nn; i += 256) us[i] = g_u[i];
    __syncthreads();
    int c = threadIdx.x & 31, g = threadIdx.x >> 5;
    int colbase = blockIdx.x * 64;
    const __nv_bfloat16* Kc = g_K16 + colbase + 2 * c;
    float accx = 0.f, accy = 0.f;
#pragma unroll 4
    for (int r = g; r < Nn; r += 8) {
        __nv_bfloat162 kk = *(const __nv_bfloat162*)(Kc + (size_t)r * Mm);
        float2 kf = __bfloat1622float2(kk);
        float ur = us[r];
        accx += kf.x * ur;
        accy += kf.y * ur;
    }
    part[g][2 * c] = accx;
    part[g][2 * c + 1] = accy;
    __syncthreads();
    if (threadIdx.x < 64) {
        float s = 0.f;
#pragma unroll
        for (int p = 0; p < 8; p++) s += part[p][threadIdx.x];
        g_v[colbase + threadIdx.x] = sqrtf((1.0f / Mm) / s);
    }
}

// ---------------------------------------------------------------------------
// T = A * (u * exp(A) * v), written into d_out's T region (fp32 K recomputed).
// ---------------------------------------------------------------------------
__global__ void __launch_bounds__(256) finalize_T(float* __restrict__ T) {
    int row = blockIdx.x;
    float u = g_u[row];
    size_t base = (size_t)row * Mm;
    const float4* A4 = (const float4*)(g_A + base);
    const float4* v4 = (const float4*)g_v;
    float4* T4 = (float4*)(T + base);
    for (int q = threadIdx.x; q < Mm / 4; q += 256) {
        float4 a = A4[q], vv = v4[q];
        T4[q] = make_float4(a.x * u * expf(a.x) * vv.x,
                            a.y * u * expf(a.y) * vv.y,
                            a.z * u * expf(a.z) * vv.z,
                            a.w * u * expf(a.w) * vv.w);
    }
}

// ---------------------------------------------------------------------------
// GEMM2 (TN), double-buffered: C[j][k] = sum_i T[i][j] * X[i][k]
// ---------------------------------------------------------------------------
__global__ void __launch_bounds__(256, 2) gemm_tn(const float* __restrict__ T,
                                                  const float* __restrict__ X,
                                                  float* __restrict__ C) {
    __shared__ float Ts[2][16][128];
    __shared__ float Xs[2][16][128];
    int bj = blockIdx.y;   // tile over M (rows of C)
    int bk = blockIdx.x;   // tile over D (cols of C)
    int tid = threadIdx.x;
    int tx = tid & 15, ty = tid >> 4;
    int lr = tid >> 5;          // 0..7
    int lc = (tid & 31) * 4;    // 0..124

    float acc[8][8];
#pragma unroll
    for (int i = 0; i < 8; i++)
#pragma unroll
        for (int j = 0; j < 8; j++) acc[i][j] = 0.f;

    float4 rt[2], rx[2];
    // prologue: tile 0
#pragma unroll
    for (int q = 0; q < 2; q++) {
        int r = lr + q * 8;
        rt[q] = *(const float4*)(T + (size_t)r * Mm + bj * 128 + lc);
        rx[q] = *(const float4*)(X + (size_t)r * Dd + bk * 128 + lc);
    }
#pragma unroll
    for (int q = 0; q < 2; q++) {
        int r = lr + q * 8;
        *(float4*)&Ts[0][r][lc] = rt[q];
        *(float4*)&Xs[0][r][lc] = rx[q];
    }
    __syncthreads();

    const int NT = Nn / 16;
    for (int kt = 0; kt < NT; kt++) {
        int buf = kt & 1;
        if (kt + 1 < NT) {
            int i0 = (kt + 1) * 16;
#pragma unroll
            for (int q = 0; q < 2; q++) {
                int r = lr + q * 8;
                rt[q] = *(const float4*)(T + (size_t)(i0 + r) * Mm + bj * 128 + lc);
                rx[q] = *(const float4*)(X + (size_t)(i0 + r) * Dd + bk * 128 + lc);
            }
        }
#pragma unroll
        for (int kk = 0; kk < 16; kk++) {
            float a[8], b[8];
            *(float4*)&a[0] = *(const float4*)&Ts[buf][kk][ty * 4];
            *(float4*)&a[4] = *(const float4*)&Ts[buf][kk][64 + ty * 4];
            *(float4*)&b[0] = *(const float4*)&Xs[buf][kk][tx * 4];
            *(float4*)&b[4] = *(const float4*)&Xs[buf][kk][64 + tx * 4];
#pragma unroll
            for (int i = 0; i < 8; i++)
#pragma unroll
                for (int j = 0; j < 8; j++)
                    acc[i][j] = fmaf(a[i], b[j], acc[i][j]);
        }
        if (kt + 1 < NT) {
            int nb = 1 - buf;
#pragma unroll
            for (int q = 0; q < 2; q++) {
                int r = lr + q * 8;
                *(float4*)&Ts[nb][r][lc] = rt[q];
                *(float4*)&Xs[nb][r][lc] = rx[q];
            }
            __syncthreads();
        }
    }

#pragma unroll
    for (int ih = 0; ih < 2; ih++)
#pragma unroll
    for (int i = 0; i < 4; i++) {
        int row = bj * 128 + ih * 64 + ty * 4 + i;
        size_t base = (size_t)row * Dd + bk * 128;
#pragma unroll
        for (int jh = 0; jh < 2; jh++) {
            int col = jh * 64 + tx * 4;
            *(float4*)&C[base + col] =
                make_float4(acc[ih * 4 + i][jh * 4 + 0],
                            acc[ih * 4 + i][jh * 4 + 1],
                            acc[ih * 4 + i][jh * 4 + 2],
                            acc[ih * 4 + i][jh * 4 + 3]);
        }
    }
}

// ---------------------------------------------------------------------------
extern "C" void kernel_launch(void* const* d_in, const int* in_sizes, int n_in,
                              void* d_out, int out_size) {
    const float* X = (const float*)d_in[0];   // source [4096,1024]
    const float* Y = (const float*)d_in[1];   // target [4096,1024]
    float* out = (float*)d_out;
    float* aligned = out;                          // [4096,1024]
    float* Tmat = out + (size_t)Mm * Dd;           // [4096,4096]

    normalize_rows<<<Nn, 256>>>(X, 0);
    normalize_rows<<<Mm, 256>>>(Y, 1);

    dim3 g1(Mm / 128, Nn / 128);
    gemm_nt_exp<<<g1, 256>>>();

    init_uv<<<Nn / 256, 256>>>();
    for (int it = 0; it < NITER; it++) {
        rowpass<<<Nn / 8, 256>>>();
        colpass<<<Mm / 64, 256>>>();
    }

    finalize_T<<<Nn, 256>>>(Tmat);

    dim3 g2(Dd / 128, Mm / 128);
    gemm_tn<<<g2, 256>>>(Tmat, X, aligned);
}

// round 4
// speedup vs baseline: 7.5121x; 2.1619x over previous
#include <cuda_runtime.h>
#include <cuda_bf16.h>
#include <math.h>
#include <stdint.h>

#define Nn 4096
#define Mm 4096
#define Dd 1024
#define NITER 20

// ---------------------------------------------------------------------------
// Static device scratch (no runtime allocation allowed).
// ---------------------------------------------------------------------------
static __device__ __nv_bfloat16 g_xh[(size_t)Nn * Dd];
static __device__ __nv_bfloat16 g_xl[(size_t)Nn * Dd];
static __device__ __nv_bfloat16 g_yh[(size_t)Mm * Dd];
static __device__ __nv_bfloat16 g_yl[(size_t)Mm * Dd];
static __device__ float         g_A[(size_t)Nn * Mm];
static __device__ __nv_bfloat16 g_K16[(size_t)Nn * Mm];
static __device__ __nv_bfloat16 g_Tth[(size_t)Mm * Nn];
static __device__ __nv_bfloat16 g_Ttl[(size_t)Mm * Nn];
static __device__ __nv_bfloat16 g_Xth[(size_t)Dd * Nn];
static __device__ __nv_bfloat16 g_Xtl[(size_t)Dd * Nn];
static __device__ float g_u[Nn];
static __device__ float g_v[Mm];

// ---------------------------------------------------------------------------
// PTX helpers: baseline (non-arch-gated) tensor path
// ---------------------------------------------------------------------------
__device__ __forceinline__ uint32_t smem_u32(const void* p) {
    uint32_t a;
    asm("{ .reg .u64 t; cvta.to.shared.u64 t, %1; cvt.u32.u64 %0, t; }"
        : "=r"(a) : "l"(p));
    return a;
}

__device__ __forceinline__ void cp16(uint32_t saddr, const void* g) {
    asm volatile("cp.async.cg.shared.global [%0], [%1], 16;" :: "r"(saddr), "l"(g) : "memory");
}
#define CP_COMMIT() asm volatile("cp.async.commit_group;" ::: "memory")
#define CP_WAIT(n)  asm volatile("cp.async.wait_group %0;" :: "n"(n) : "memory")

__device__ __forceinline__ void ldsm_x4(uint32_t* r, uint32_t addr) {
    asm volatile("ldmatrix.sync.aligned.m8n8.x4.shared.b16 {%0,%1,%2,%3}, [%4];"
        : "=r"(r[0]), "=r"(r[1]), "=r"(r[2]), "=r"(r[3]) : "r"(addr));
}
__device__ __forceinline__ void ldsm_x2(uint32_t* r, uint32_t addr) {
    asm volatile("ldmatrix.sync.aligned.m8n8.x2.shared.b16 {%0,%1}, [%2];"
        : "=r"(r[0]), "=r"(r[1]) : "r"(addr));
}
__device__ __forceinline__ void mma_bf16(float* d, const uint32_t* a, const uint32_t* b) {
    asm volatile("mma.sync.aligned.m16n8k16.row.col.f32.bf16.bf16.f32 "
        "{%0,%1,%2,%3}, {%4,%5,%6,%7}, {%8,%9}, {%0,%1,%2,%3};"
        : "+f"(d[0]), "+f"(d[1]), "+f"(d[2]), "+f"(d[3])
        : "r"(a[0]), "r"(a[1]), "r"(a[2]), "r"(a[3]), "r"(b[0]), "r"(b[1]));
}

// ---------------------------------------------------------------------------
// Row L2-normalize -> bf16 hi/lo split
// ---------------------------------------------------------------------------
__global__ void __launch_bounds__(256) normalize_rows(const float* __restrict__ in, int which) {
    int row = blockIdx.x;
    const float4* src = (const float4*)(in + (size_t)row * Dd);
    float4 val = src[threadIdx.x];
    float ss = val.x * val.x + val.y * val.y + val.z * val.z + val.w * val.w;
#pragma unroll
    for (int o = 16; o; o >>= 1) ss += __shfl_xor_sync(0xffffffffu, ss, o);
    __shared__ float wsum[8];
    int lane = threadIdx.x & 31, warp = threadIdx.x >> 5;
    if (!lane) wsum[warp] = ss;
    __syncthreads();
    float tot = 0.f;
#pragma unroll
    for (int p = 0; p < 8; p++) tot += wsum[p];
    float inv = rsqrtf(tot);
    float o4[4] = {val.x * inv, val.y * inv, val.z * inv, val.w * inv};
    __nv_bfloat16 h[4], l[4];
#pragma unroll
    for (int c = 0; c < 4; c++) {
        h[c] = __float2bfloat16(o4[c]);
        l[c] = __float2bfloat16(o4[c] - __bfloat162float(h[c]));
    }
    size_t off = (size_t)row * Dd + threadIdx.x * 4;
    __nv_bfloat16* dh = (which ? g_yh : g_xh) + off;
    __nv_bfloat16* dl = (which ? g_yl : g_xl) + off;
    *(uint2*)dh = *(uint2*)h;
    *(uint2*)dl = *(uint2*)l;
}

// ---------------------------------------------------------------------------
// Transpose X -> Xt hi/lo bf16  ([4096,1024] -> [1024,4096])
// ---------------------------------------------------------------------------
__global__ void __launch_bounds__(256) transpose_X(const float* __restrict__ X) {
    __shared__ float s[32][33];
    int j0 = blockIdx.x * 32;
    int i0 = blockIdx.y * 32;
    int tx = threadIdx.x & 31, ty = threadIdx.x >> 5;
#pragma unroll
    for (int r = 0; r < 4; r++)
        s[ty + r * 8][tx] = X[(size_t)(i0 + ty + r * 8) * Dd + j0 + tx];
    __syncthreads();
#pragma unroll
    for (int r = 0; r < 4; r++) {
        int orow = j0 + ty + r * 8;
        float t = s[tx][ty + r * 8];
        __nv_bfloat16 h = __float2bfloat16(t);
        __nv_bfloat16 l = __float2bfloat16(t - __bfloat162float(h));
        g_Xth[(size_t)orow * Nn + i0 + tx] = h;
        g_Xtl[(size_t)orow * Nn + i0 + tx] = l;
    }
}

// ---------------------------------------------------------------------------
// mma.sync bf16x3 GEMM (NT, K-major operands), 128x128 tile, BK=64.
// mode 0: D = xn . yn^T  -> writes g_A (fp32) + g_K16 (bf16 exp)
// mode 1: D = Tt . Xt^T  -> writes Cout (aligned, ld=Dd)
// ---------------------------------------------------------------------------
#define TILE_B 16384
#define STAGE_B (4 * TILE_B)
#define GEMM_SMEM (2 * STAGE_B)

// 128 rows x 64 bf16 (128B) per tile, XOR-swizzled 16B chunks.
__device__ __forceinline__ void load_stage(
    const __nv_bfloat16* __restrict__ Ah, const __nv_bfloat16* __restrict__ Al,
    const __nv_bfloat16* __restrict__ Bh, const __nv_bfloat16* __restrict__ Bl,
    int ldA, int ldB, int rowA, int rowB, int k0, uint32_t sb, int tid)
{
#pragma unroll
    for (int it = 0; it < 4; it++) {
        int i = tid + it * 256;
        int r = i >> 3, c = i & 7;
        uint32_t off = (uint32_t)((r << 7) | (c << 4));
        uint32_t sw = off ^ ((uint32_t)(r & 7) << 4);
        size_t ga = (size_t)(rowA + r) * ldA + k0 + c * 8;
        size_t gb = (size_t)(rowB + r) * ldB + k0 + c * 8;
        cp16(sb + sw,              Ah + ga);
        cp16(sb + TILE_B + sw,     Al + ga);
        cp16(sb + 2 * TILE_B + sw, Bh + gb);
        cp16(sb + 3 * TILE_B + sw, Bl + gb);
    }
}

__global__ void __launch_bounds__(256) gemm_bf16x3(int mode, float* __restrict__ Cout) {
    extern __shared__ char smem[];
    uint32_t sbase = smem_u32(smem);
    int tid = threadIdx.x;
    int lane = tid & 31, wid = tid >> 5;
    int wm = wid >> 2, wn = wid & 3;      // warp grid 2 x 4 -> warp tile 64 x 32

    const __nv_bfloat16 *Ah, *Al, *Bh, *Bl;
    int K, ldA, ldB;
    if (mode == 0) { Ah = g_xh;  Al = g_xl;  Bh = g_yh;  Bl = g_yl;  K = Dd; ldA = Dd; ldB = Dd; }
    else           { Ah = g_Tth; Al = g_Ttl; Bh = g_Xth; Bl = g_Xtl; K = Nn; ldA = Nn; ldB = Nn; }

    int bm = blockIdx.y, bn = blockIdx.x;
    int rowA = bm * 128, rowB = bn * 128;

    float acc[4][4][4];
#pragma unroll
    for (int a = 0; a < 4; a++)
#pragma unroll
        for (int b = 0; b < 4; b++)
#pragma unroll
            for (int c = 0; c < 4; c++) acc[a][b][c] = 0.f;

    // lane-invariant fragment addressing
    int arow = wm * 64 + (lane & 7) + 8 * ((lane >> 3) & 1);
    uint32_t akb = 16u * (lane >> 4);
    int brow = wn * 32 + (lane & 7);
    uint32_t bkb = 16u * ((lane >> 3) & 1);
    uint32_t xorA = (uint32_t)(arow & 7) << 4;
    uint32_t xorB = (uint32_t)(brow & 7) << 4;
    uint32_t aRB = (uint32_t)arow << 7;   // row byte offset
    uint32_t bRB = (uint32_t)brow << 7;

    const int NT = K / 64;

    load_stage(Ah, Al, Bh, Bl, ldA, ldB, rowA, rowB, 0, sbase, tid);
    CP_COMMIT();

    for (int kt = 0; kt < NT; kt++) {
        uint32_t sb = sbase + (uint32_t)(kt & 1) * STAGE_B;
        if (kt + 1 < NT) {
            load_stage(Ah, Al, Bh, Bl, ldA, ldB, rowA, rowB, (kt + 1) * 64,
                       sbase + (uint32_t)((kt + 1) & 1) * STAGE_B, tid);
            CP_COMMIT();
            CP_WAIT(1);
        } else {
            CP_WAIT(0);
        }
        __syncthreads();

        uint32_t sAh = sb, sAl = sb + TILE_B, sBh = sb + 2 * TILE_B, sBl = sb + 3 * TILE_B;
#pragma unroll
        for (int ks = 0; ks < 4; ks++) {
            uint32_t ca = (akb + 32u * ks) ^ xorA;
            uint32_t cb = (bkb + 32u * ks) ^ xorB;
            uint32_t fAh[4][4], fAl[4][4];
#pragma unroll
            for (int mt = 0; mt < 4; mt++) {
                uint32_t ao = aRB + (uint32_t)mt * 2048 + ca;
                ldsm_x4(fAh[mt], sAh + ao);
                ldsm_x4(fAl[mt], sAl + ao);
            }
#pragma unroll
            for (int nt = 0; nt < 4; nt++) {
                uint32_t bo = bRB + (uint32_t)nt * 1024 + cb;
                uint32_t fBh[2], fBl[2];
                ldsm_x2(fBh, sBh + bo);
                ldsm_x2(fBl, sBl + bo);
#pragma unroll
                for (int mt = 0; mt < 4; mt++) {
                    mma_bf16(acc[mt][nt], fAh[mt], fBh);
                    mma_bf16(acc[mt][nt], fAh[mt], fBl);
                    mma_bf16(acc[mt][nt], fAl[mt], fBh);
                }
            }
        }
        __syncthreads();
    }

    // epilogue from registers
    int r0 = bm * 128 + wm * 64 + (lane >> 2);
    int c0 = bn * 128 + wn * 32 + (lane & 3) * 2;
    if (mode == 0) {
#pragma unroll
        for (int mt = 0; mt < 4; mt++)
#pragma unroll
            for (int half = 0; half < 2; half++) {
                int row = r0 + mt * 16 + half * 8;
                size_t base = (size_t)row * Mm;
#pragma unroll
                for (int nt = 0; nt < 4; nt++) {
                    float d0 = acc[mt][nt][half * 2 + 0];
                    float d1 = acc[mt][nt][half * 2 + 1];
                    int col = c0 + nt * 8;
                    *(float2*)&g_A[base + col] = make_float2(d0, d1);
                    __nv_bfloat162 kp = __floats2bfloat162_rn(expf(d0), expf(d1));
                    *(__nv_bfloat162*)&g_K16[base + col] = kp;
                }
            }
    } else {
#pragma unroll
        for (int mt = 0; mt < 4; mt++)
#pragma unroll
            for (int half = 0; half < 2; half++) {
                int row = r0 + mt * 16 + half * 8;
                size_t base = (size_t)row * Dd;
#pragma unroll
                for (int nt = 0; nt < 4; nt++) {
                    int col = c0 + nt * 8;
                    *(float2*)&Cout[base + col] =
                        make_float2(acc[mt][nt][half * 2 + 0], acc[mt][nt][half * 2 + 1]);
                }
            }
    }
}

// ---------------------------------------------------------------------------
// Sinkhorn (bf16 K, fp32 accumulate)
// ---------------------------------------------------------------------------
__global__ void init_uv() {
    int i = blockIdx.x * 256 + threadIdx.x;
    g_u[i] = 1.0f / Nn;
    g_v[i] = 1.0f / Mm;
}

__global__ void __launch_bounds__(256) rowpass() {
    int warp = threadIdx.x >> 5, lane = threadIdx.x & 31;
    int row = (blockIdx.x << 3) + warp;
    const uint4* Kr = (const uint4*)(g_K16 + (size_t)row * Mm);
    const float4* v4 = (const float4*)g_v;
    float acc = 0.f;
#pragma unroll 4
    for (int j = lane; j < Mm / 8; j += 32) {
        uint4 kq = Kr[j];
        float4 va = v4[2 * j], vb = v4[2 * j + 1];
        float2 k0 = __bfloat1622float2(*(__nv_bfloat162*)&kq.x);
        float2 k1 = __bfloat1622float2(*(__nv_bfloat162*)&kq.y);
        float2 k2 = __bfloat1622float2(*(__nv_bfloat162*)&kq.z);
        float2 k3 = __bfloat1622float2(*(__nv_bfloat162*)&kq.w);
        acc += k0.x * va.x + k0.y * va.y + k1.x * va.z + k1.y * va.w
             + k2.x * vb.x + k2.y * vb.y + k3.x * vb.z + k3.y * vb.w;
    }
#pragma unroll
    for (int o = 16; o; o >>= 1) acc += __shfl_xor_sync(0xffffffffu, acc, o);
    if (!lane) g_u[row] = sqrtf((1.0f / Nn) / acc);
}

__global__ void __launch_bounds__(256) colpass() {
    __shared__ float us[Nn];
    __shared__ float part[8][66];
    for (int i = threadIdx.x; i < Nn; i += 256) us[i] = g_u[i];
    __syncthreads();
    int c = threadIdx.x & 31, g = threadIdx.x >> 5;
    int colbase = blockIdx.x * 64;
    const __nv_bfloat16* Kc = g_K16 + colbase + 2 * c;
    float accx = 0.f, accy = 0.f;
#pragma unroll 4
    for (int r = g; r < Nn; r += 8) {
        __nv_bfloat162 kk = *(const __nv_bfloat162*)(Kc + (size_t)r * Mm);
        float2 kf = __bfloat1622float2(kk);
        float ur = us[r];
        accx += kf.x * ur;
        accy += kf.y * ur;
    }
    part[g][2 * c] = accx;
    part[g][2 * c + 1] = accy;
    __syncthreads();
    if (threadIdx.x < 64) {
        float s = 0.f;
#pragma unroll
        for (int p = 0; p < 8; p++) s += part[p][threadIdx.x];
        g_v[colbase + threadIdx.x] = sqrtf((1.0f / Mm) / s);
    }
}

// ---------------------------------------------------------------------------
// finalize: T = A*u*exp(A)*v (fp32, to d_out), plus Tt hi/lo bf16 (transposed)
// ---------------------------------------------------------------------------
__global__ void __launch_bounds__(256) finalize_T(float* __restrict__ T) {
    __shared__ float s[32][33];
    int j0 = blockIdx.x * 32, i0 = blockIdx.y * 32;
    int tx = threadIdx.x & 31, ty = threadIdx.x >> 5;
    float vj = g_v[j0 + tx];
#pragma unroll
    for (int r = 0; r < 4; r++) {
        int row = i0 + ty + r * 8;
        float a = g_A[(size_t)row * Mm + j0 + tx];
        float t = a * g_u[row] * expf(a) * vj;
        T[(size_t)row * Mm + j0 + tx] = t;
        s[ty + r * 8][tx] = t;
    }
    __syncthreads();
#pragma unroll
    for (int r = 0; r < 4; r++) {
        int orow = j0 + ty + r * 8;
        float t = s[tx][ty + r * 8];
        __nv_bfloat16 h = __float2bfloat16(t);
        __nv_bfloat16 l = __float2bfloat16(t - __bfloat162float(h));
        g_Tth[(size_t)orow * Nn + i0 + tx] = h;
        g_Ttl[(size_t)orow * Nn + i0 + tx] = l;
    }
}

// ---------------------------------------------------------------------------
extern "C" void kernel_launch(void* const* d_in, const int* in_sizes, int n_in,
                              void* d_out, int out_size) {
    const float* X = (const float*)d_in[0];   // source [4096,1024]
    const float* Y = (const float*)d_in[1];   // target [4096,1024]
    float* out = (float*)d_out;
    float* aligned = out;                          // [4096,1024]
    float* Tmat = out + (size_t)Mm * Dd;           // [4096,4096]

    cudaFuncSetAttribute(gemm_bf16x3, cudaFuncAttributeMaxDynamicSharedMemorySize, GEMM_SMEM);

    normalize_rows<<<Nn, 256>>>(X, 0);
    normalize_rows<<<Mm, 256>>>(Y, 1);
    transpose_X<<<dim3(Dd / 32, Nn / 32), 256>>>(X);

    gemm_bf16x3<<<dim3(Mm / 128, Nn / 128), 256, GEMM_SMEM>>>(0, nullptr);

    init_uv<<<Nn / 256, 256>>>();
    for (int it = 0; it < NITER; it++) {
        rowpass<<<Nn / 8, 256>>>();
        colpass<<<Mm / 64, 256>>>();
    }

    finalize_T<<<dim3(Mm / 32, Nn / 32), 256>>>(Tmat);

    gemm_bf16x3<<<dim3(Dd / 128, Mm / 128), 256, GEMM_SMEM>>>(1, aligned);
}

// round 5
// speedup vs baseline: 10.7001x; 1.4244x over previous
#include <cuda_runtime.h>
#include <cuda_bf16.h>
#include <math.h>
#include <stdint.h>

#define Nn 4096
#define Mm 4096
#define Dd 1024
#define NITER 12
#define ROWS_PB 32
#define NBLK (Nn / ROWS_PB)   // 128

// ---------------------------------------------------------------------------
// Static device scratch (no runtime allocation allowed).
// ---------------------------------------------------------------------------
static __device__ __nv_bfloat16 g_xh[(size_t)Nn * Dd];
static __device__ __nv_bfloat16 g_xl[(size_t)Nn * Dd];
static __device__ __nv_bfloat16 g_yh[(size_t)Mm * Dd];
static __device__ __nv_bfloat16 g_yl[(size_t)Mm * Dd];
static __device__ float         g_A[(size_t)Nn * Mm];
static __device__ __nv_bfloat16 g_K16[(size_t)Nn * Mm];
static __device__ __nv_bfloat16 g_Tth[(size_t)Mm * Nn];
static __device__ __nv_bfloat16 g_Ttl[(size_t)Mm * Nn];
static __device__ __nv_bfloat16 g_Xth[(size_t)Dd * Nn];
static __device__ __nv_bfloat16 g_Xtl[(size_t)Dd * Nn];
static __device__ float g_u[Nn];
static __device__ float g_v[Mm];
static __device__ float g_part[(size_t)NBLK * Mm];

// ---------------------------------------------------------------------------
// PTX helpers (baseline, non-arch-gated)
// ---------------------------------------------------------------------------
__device__ __forceinline__ uint32_t smem_u32(const void* p) {
    uint32_t a;
    asm("{ .reg .u64 t; cvta.to.shared.u64 t, %1; cvt.u32.u64 %0, t; }"
        : "=r"(a) : "l"(p));
    return a;
}
__device__ __forceinline__ void cp16(uint32_t saddr, const void* g) {
    asm volatile("cp.async.cg.shared.global [%0], [%1], 16;" :: "r"(saddr), "l"(g) : "memory");
}
#define CP_COMMIT() asm volatile("cp.async.commit_group;" ::: "memory")
#define CP_WAIT(n)  asm volatile("cp.async.wait_group %0;" :: "n"(n) : "memory")

__device__ __forceinline__ void ldsm_x4(uint32_t* r, uint32_t addr) {
    asm volatile("ldmatrix.sync.aligned.m8n8.x4.shared.b16 {%0,%1,%2,%3}, [%4];"
        : "=r"(r[0]), "=r"(r[1]), "=r"(r[2]), "=r"(r[3]) : "r"(addr));
}
__device__ __forceinline__ void mma_bf16(float* d, const uint32_t* a, const uint32_t* b) {
    asm volatile("mma.sync.aligned.m16n8k16.row.col.f32.bf16.bf16.f32 "
        "{%0,%1,%2,%3}, {%4,%5,%6,%7}, {%8,%9}, {%0,%1,%2,%3};"
        : "+f"(d[0]), "+f"(d[1]), "+f"(d[2]), "+f"(d[3])
        : "r"(a[0]), "r"(a[1]), "r"(a[2]), "r"(a[3]), "r"(b[0]), "r"(b[1]));
}

// ---------------------------------------------------------------------------
// Row L2-normalize -> bf16 hi/lo split
// ---------------------------------------------------------------------------
__global__ void __launch_bounds__(256) normalize_rows(const float* __restrict__ in, int which) {
    int row = blockIdx.x;
    const float4* src = (const float4*)(in + (size_t)row * Dd);
    float4 val = src[threadIdx.x];
    float ss = val.x * val.x + val.y * val.y + val.z * val.z + val.w * val.w;
#pragma unroll
    for (int o = 16; o; o >>= 1) ss += __shfl_xor_sync(0xffffffffu, ss, o);
    __shared__ float wsum[8];
    int lane = threadIdx.x & 31, warp = threadIdx.x >> 5;
    if (!lane) wsum[warp] = ss;
    __syncthreads();
    float tot = 0.f;
#pragma unroll
    for (int p = 0; p < 8; p++) tot += wsum[p];
    float inv = rsqrtf(tot);
    float o4[4] = {val.x * inv, val.y * inv, val.z * inv, val.w * inv};
    __nv_bfloat16 h[4], l[4];
#pragma unroll
    for (int c = 0; c < 4; c++) {
        h[c] = __float2bfloat16(o4[c]);
        l[c] = __float2bfloat16(o4[c] - __bfloat162float(h[c]));
    }
    size_t off = (size_t)row * Dd + threadIdx.x * 4;
    __nv_bfloat16* dh = (which ? g_yh : g_xh) + off;
    __nv_bfloat16* dl = (which ? g_yl : g_xl) + off;
    *(uint2*)dh = *(uint2*)h;
    *(uint2*)dl = *(uint2*)l;
}

// ---------------------------------------------------------------------------
// Transpose X -> Xt hi/lo bf16  ([4096,1024] -> [1024,4096])
// ---------------------------------------------------------------------------
__global__ void __launch_bounds__(256) transpose_X(const float* __restrict__ X) {
    __shared__ float s[32][33];
    int j0 = blockIdx.x * 32;
    int i0 = blockIdx.y * 32;
    int tx = threadIdx.x & 31, ty = threadIdx.x >> 5;
#pragma unroll
    for (int r = 0; r < 4; r++)
        s[ty + r * 8][tx] = X[(size_t)(i0 + ty + r * 8) * Dd + j0 + tx];
    __syncthreads();
#pragma unroll
    for (int r = 0; r < 4; r++) {
        int orow = j0 + ty + r * 8;
        float t = s[tx][ty + r * 8];
        __nv_bfloat16 h = __float2bfloat16(t);
        __nv_bfloat16 l = __float2bfloat16(t - __bfloat162float(h));
        g_Xth[(size_t)orow * Nn + i0 + tx] = h;
        g_Xtl[(size_t)orow * Nn + i0 + tx] = l;
    }
}

// ---------------------------------------------------------------------------
// mma.sync bf16x3 GEMM, 128x128 tile, BK=64, 3-stage cp.async pipeline.
// mode 0: D = xn . yn^T -> g_A (fp32) + g_K16 (bf16 exp)
// mode 1: D = Tt . Xt^T -> Cout (ld=Dd)
// ---------------------------------------------------------------------------
#define TILE_B 16384
#define STAGE_B (4 * TILE_B)
#define GEMM_SMEM (3 * STAGE_B)

__device__ __forceinline__ void load_stage(
    const __nv_bfloat16* __restrict__ Ah, const __nv_bfloat16* __restrict__ Al,
    const __nv_bfloat16* __restrict__ Bh, const __nv_bfloat16* __restrict__ Bl,
    int ldA, int ldB, int rowA, int rowB, int k0, uint32_t sb, int tid)
{
#pragma unroll
    for (int it = 0; it < 4; it++) {
        int i = tid + it * 256;
        int r = i >> 3, c = i & 7;
        uint32_t off = (uint32_t)((r << 7) | (c << 4));
        uint32_t sw = off ^ ((uint32_t)(r & 7) << 4);
        size_t ga = (size_t)(rowA + r) * ldA + k0 + c * 8;
        size_t gb = (size_t)(rowB + r) * ldB + k0 + c * 8;
        cp16(sb + sw,              Ah + ga);
        cp16(sb + TILE_B + sw,     Al + ga);
        cp16(sb + 2 * TILE_B + sw, Bh + gb);
        cp16(sb + 3 * TILE_B + sw, Bl + gb);
    }
}

__global__ void __launch_bounds__(256) gemm_bf16x3(int mode, float* __restrict__ Cout) {
    extern __shared__ char smem[];
    uint32_t sbase = smem_u32(smem);
    int tid = threadIdx.x;
    int lane = tid & 31, wid = tid >> 5;
    int wm = wid >> 2, wn = wid & 3;      // 2 x 4 warps -> warp tile 64 x 32

    const __nv_bfloat16 *Ah, *Al, *Bh, *Bl;
    int K, ldA, ldB;
    if (mode == 0) { Ah = g_xh;  Al = g_xl;  Bh = g_yh;  Bl = g_yl;  K = Dd; ldA = Dd; ldB = Dd; }
    else           { Ah = g_Tth; Al = g_Ttl; Bh = g_Xth; Bl = g_Xtl; K = Nn; ldA = Nn; ldB = Nn; }

    int bm = blockIdx.y, bn = blockIdx.x;
    int rowA = bm * 128, rowB = bn * 128;

    float acc[4][4][4];
#pragma unroll
    for (int a = 0; a < 4; a++)
#pragma unroll
        for (int b = 0; b < 4; b++)
#pragma unroll
            for (int c = 0; c < 4; c++) acc[a][b][c] = 0.f;

    // A fragment addressing (lane-invariant after precompute)
    int arow = wm * 64 + (lane & 7) + 8 * ((lane >> 3) & 1);
    uint32_t akb = 16u * (lane >> 4);
    uint32_t xorA = (uint32_t)(arow & 7) << 4;
    uint32_t aRB = (uint32_t)arow << 7;
    // B fragment addressing: x4 covers two n8 tiles (16 rows)
    int browl = (lane & 7) + 8 * (lane >> 4);
    uint32_t bkb = 16u * ((lane >> 3) & 1);
    uint32_t xorB = (uint32_t)(lane & 7) << 4;

    const int NT = K / 64;

    load_stage(Ah, Al, Bh, Bl, ldA, ldB, rowA, rowB, 0, sbase, tid);
    CP_COMMIT();
    load_stage(Ah, Al, Bh, Bl, ldA, ldB, rowA, rowB, 64, sbase + STAGE_B, tid);
    CP_COMMIT();

    for (int kt = 0; kt < NT; kt++) {
        if (kt + 2 < NT) { CP_WAIT(1); } else { CP_WAIT(0); }
        __syncthreads();
        if (kt + 2 < NT) {
            load_stage(Ah, Al, Bh, Bl, ldA, ldB, rowA, rowB, (kt + 2) * 64,
                       sbase + (uint32_t)((kt + 2) % 3) * STAGE_B, tid);
            CP_COMMIT();
        }
        uint32_t sb = sbase + (uint32_t)(kt % 3) * STAGE_B;
        uint32_t sAh = sb, sAl = sb + TILE_B, sBh = sb + 2 * TILE_B, sBl = sb + 3 * TILE_B;
#pragma unroll
        for (int ks = 0; ks < 4; ks++) {
            uint32_t ca = (akb + 32u * ks) ^ xorA;
            uint32_t cb = (bkb + 32u * ks) ^ xorB;
            uint32_t fAh[4][4], fAl[4][4], fBh[2][4], fBl[2][4];
#pragma unroll
            for (int mt = 0; mt < 4; mt++) {
                uint32_t ao = aRB + (uint32_t)mt * 2048 + ca;
                ldsm_x4(fAh[mt], sAh + ao);
                ldsm_x4(fAl[mt], sAl + ao);
            }
#pragma unroll
            for (int nt2 = 0; nt2 < 2; nt2++) {
                uint32_t bo = ((uint32_t)(wn * 32 + nt2 * 16 + browl) << 7) + cb;
                ldsm_x4(fBh[nt2], sBh + bo);
                ldsm_x4(fBl[nt2], sBl + bo);
            }
#pragma unroll
            for (int nt2 = 0; nt2 < 2; nt2++)
#pragma unroll
                for (int mt = 0; mt < 4; mt++) {
                    mma_bf16(acc[mt][2 * nt2],     fAh[mt], &fBh[nt2][0]);
                    mma_bf16(acc[mt][2 * nt2],     fAh[mt], &fBl[nt2][0]);
                    mma_bf16(acc[mt][2 * nt2],     fAl[mt], &fBh[nt2][0]);
                    mma_bf16(acc[mt][2 * nt2 + 1], fAh[mt], &fBh[nt2][2]);
                    mma_bf16(acc[mt][2 * nt2 + 1], fAh[mt], &fBl[nt2][2]);
                    mma_bf16(acc[mt][2 * nt2 + 1], fAl[mt], &fBh[nt2][2]);
                }
        }
    }

    int r0 = bm * 128 + wm * 64 + (lane >> 2);
    int c0 = bn * 128 + wn * 32 + (lane & 3) * 2;
    if (mode == 0) {
#pragma unroll
        for (int mt = 0; mt < 4; mt++)
#pragma unroll
            for (int half = 0; half < 2; half++) {
                int row = r0 + mt * 16 + half * 8;
                size_t base = (size_t)row * Mm;
#pragma unroll
                for (int nt = 0; nt < 4; nt++) {
                    float d0 = acc[mt][nt][half * 2 + 0];
                    float d1 = acc[mt][nt][half * 2 + 1];
                    int col = c0 + nt * 8;
                    *(float2*)&g_A[base + col] = make_float2(d0, d1);
                    __nv_bfloat162 kp = __floats2bfloat162_rn(expf(d0), expf(d1));
                    *(__nv_bfloat162*)&g_K16[base + col] = kp;
                }
            }
    } else {
#pragma unroll
        for (int mt = 0; mt < 4; mt++)
#pragma unroll
            for (int half = 0; half < 2; half++) {
                int row = r0 + mt * 16 + half * 8;
                size_t base = (size_t)row * Dd;
#pragma unroll
                for (int nt = 0; nt < 4; nt++) {
                    int col = c0 + nt * 8;
                    *(float2*)&Cout[base + col] =
                        make_float2(acc[mt][nt][half * 2 + 0], acc[mt][nt][half * 2 + 1]);
                }
            }
    }
}

// ---------------------------------------------------------------------------
// Sinkhorn: fused iteration. Block b owns rows [b*32, b*32+32).
// Phase 1: u_i = sqrt(a/(K v)_i). Phase 2: per-block column partials of K^T u.
// ---------------------------------------------------------------------------
__global__ void init_uv() {
    int i = blockIdx.x * 256 + threadIdx.x;
    g_u[i] = 1.0f / Nn;
    g_v[i] = 1.0f / Mm;
}

__global__ void __launch_bounds__(256) sink_iter() {
    __shared__ float ush[ROWS_PB];
    int tid = threadIdx.x;
    int warp = tid >> 5, lane = tid & 31;
    int row0 = blockIdx.x * ROWS_PB;

    // Phase 1: each warp handles 4 rows
#pragma unroll
    for (int rr = 0; rr < 4; rr++) {
        int rl = warp * 4 + rr;
        const uint4* Kr = (const uint4*)(g_K16 + (size_t)(row0 + rl) * Mm);
        const float4* v4 = (const float4*)g_v;
        float acc = 0.f;
#pragma unroll 4
        for (int j = lane; j < Mm / 8; j += 32) {
            uint4 kq = Kr[j];
            float4 va = v4[2 * j], vb = v4[2 * j + 1];
            float2 k0 = __bfloat1622float2(*(__nv_bfloat162*)&kq.x);
            float2 k1 = __bfloat1622float2(*(__nv_bfloat162*)&kq.y);
            float2 k2 = __bfloat1622float2(*(__nv_bfloat162*)&kq.z);
            float2 k3 = __bfloat1622float2(*(__nv_bfloat162*)&kq.w);
            acc += k0.x * va.x + k0.y * va.y + k1.x * va.z + k1.y * va.w
                 + k2.x * vb.x + k2.y * vb.y + k3.x * vb.z + k3.y * vb.w;
        }
#pragma unroll
        for (int o = 16; o; o >>= 1) acc += __shfl_xor_sync(0xffffffffu, acc, o);
        if (!lane) {
            float u = sqrtf((1.0f / Nn) / acc);
            ush[rl] = u;
            g_u[row0 + rl] = u;
        }
    }
    __syncthreads();

    // Phase 2: column partials (block's 256KB K slice is L2-hot)
#pragma unroll
    for (int t = 0; t < 8; t++) {
        int j = tid * 2 + t * 512;
        float ax = 0.f, ay = 0.f;
#pragma unroll 8
        for (int i = 0; i < ROWS_PB; i++) {
            __nv_bfloat162 kk = *(const __nv_bfloat162*)(g_K16 + (size_t)(row0 + i) * Mm + j);
            float2 kf = __bfloat1622float2(kk);
            float u = ush[i];
            ax += kf.x * u;
            ay += kf.y * u;
        }
        *(float2*)&g_part[(size_t)blockIdx.x * Mm + j] = make_float2(ax, ay);
    }
}

__global__ void __launch_bounds__(256) sink_vfin() {
    int j = blockIdx.x * 256 + threadIdx.x;
    float s = 0.f;
#pragma unroll 8
    for (int b = 0; b < NBLK; b++) s += g_part[(size_t)b * Mm + j];
    g_v[j] = sqrtf((1.0f / Mm) / s);
}

// ---------------------------------------------------------------------------
// finalize: T = A*u*exp(A)*v (fp32 -> d_out), plus Tt hi/lo bf16 (transposed)
// ---------------------------------------------------------------------------
__global__ void __launch_bounds__(256) finalize_T(float* __restrict__ T) {
    __shared__ float s[32][33];
    int j0 = blockIdx.x * 32, i0 = blockIdx.y * 32;
    int tx = threadIdx.x & 31, ty = threadIdx.x >> 5;
    float vj = g_v[j0 + tx];
#pragma unroll
    for (int r = 0; r < 4; r++) {
        int row = i0 + ty + r * 8;
        float a = g_A[(size_t)row * Mm + j0 + tx];
        float t = a * g_u[row] * expf(a) * vj;
        T[(size_t)row * Mm + j0 + tx] = t;
        s[ty + r * 8][tx] = t;
    }
    __syncthreads();
#pragma unroll
    for (int r = 0; r < 4; r++) {
        int orow = j0 + ty + r * 8;
        float t = s[tx][ty + r * 8];
        __nv_bfloat16 h = __float2bfloat16(t);
        __nv_bfloat16 l = __float2bfloat16(t - __bfloat162float(h));
        g_Tth[(size_t)orow * Nn + i0 + tx] = h;
        g_Ttl[(size_t)orow * Nn + i0 + tx] = l;
    }
}

// ---------------------------------------------------------------------------
extern "C" void kernel_launch(void* const* d_in, const int* in_sizes, int n_in,
                              void* d_out, int out_size) {
    const float* X = (const float*)d_in[0];
    const float* Y = (const float*)d_in[1];
    float* out = (float*)d_out;
    float* aligned = out;                          // [4096,1024]
    float* Tmat = out + (size_t)Mm * Dd;           // [4096,4096]

    cudaFuncSetAttribute(gemm_bf16x3, cudaFuncAttributeMaxDynamicSharedMemorySize, GEMM_SMEM);

    normalize_rows<<<Nn, 256>>>(X, 0);
    normalize_rows<<<Mm, 256>>>(Y, 1);
    transpose_X<<<dim3(Dd / 32, Nn / 32), 256>>>(X);

    gemm_bf16x3<<<dim3(Mm / 128, Nn / 128), 256, GEMM_SMEM>>>(0, nullptr);

    init_uv<<<Nn / 256, 256>>>();
    for (int it = 0; it < NITER; it++) {
        sink_iter<<<NBLK, 256>>>();
        sink_vfin<<<Mm / 256, 256>>>();
    }

    finalize_T<<<dim3(Mm / 32, Nn / 32), 256>>>(Tmat);

    gemm_bf16x3<<<dim3(Dd / 128, Mm / 128), 256, GEMM_SMEM>>>(1, aligned);
}

// round 6
// speedup vs baseline: 11.6966x; 1.0931x over previous
#include <cuda_runtime.h>
#include <cuda_bf16.h>
#include <cuda_fp16.h>
#include <math.h>
#include <stdint.h>

#define Nn 4096
#define Mm 4096
#define Dd 1024
#define NITER 12
#define ROWS_PB 32
#define NBLK (Nn / ROWS_PB)   // 128

#define TSCALE 67108864.0f        // 2^26
#define TSCALE_INV 1.4901161193847656e-8f  // 2^-26
#define EPI1 0.0009765625f        // 2^-10 (both operands scaled by 32)

// ---------------------------------------------------------------------------
// Static device scratch (no runtime allocation allowed).
// ---------------------------------------------------------------------------
static __device__ __half g_xh[(size_t)Nn * Dd];
static __device__ __half g_xl[(size_t)Nn * Dd];
static __device__ __half g_yh[(size_t)Mm * Dd];
static __device__ float  g_A[(size_t)Nn * Mm];
static __device__ __nv_bfloat16 g_K16[(size_t)Nn * Mm];
static __device__ __half g_Tth[(size_t)Mm * Nn];
static __device__ __half g_Ttl[(size_t)Mm * Nn];
static __device__ __half g_Xth[(size_t)Dd * Nn];
static __device__ float g_u[Nn];
static __device__ float g_v[Mm];
static __device__ float g_part[(size_t)NBLK * Mm];

// ---------------------------------------------------------------------------
// PTX helpers (baseline, non-arch-gated)
// ---------------------------------------------------------------------------
__device__ __forceinline__ uint32_t smem_u32(const void* p) {
    uint32_t a;
    asm("{ .reg .u64 t; cvta.to.shared.u64 t, %1; cvt.u32.u64 %0, t; }"
        : "=r"(a) : "l"(p));
    return a;
}
__device__ __forceinline__ void cp16(uint32_t saddr, const void* g) {
    asm volatile("cp.async.cg.shared.global [%0], [%1], 16;" :: "r"(saddr), "l"(g) : "memory");
}
#define CP_COMMIT() asm volatile("cp.async.commit_group;" ::: "memory")
#define CP_WAIT(n)  asm volatile("cp.async.wait_group %0;" :: "n"(n) : "memory")

__device__ __forceinline__ void ldsm_x4(uint32_t* r, uint32_t addr) {
    asm volatile("ldmatrix.sync.aligned.m8n8.x4.shared.b16 {%0,%1,%2,%3}, [%4];"
        : "=r"(r[0]), "=r"(r[1]), "=r"(r[2]), "=r"(r[3]) : "r"(addr));
}
__device__ __forceinline__ void mma_fp16(float* d, const uint32_t* a, const uint32_t* b) {
    asm volatile("mma.sync.aligned.m16n8k16.row.col.f32.f16.f16.f32 "
        "{%0,%1,%2,%3}, {%4,%5,%6,%7}, {%8,%9}, {%0,%1,%2,%3};"
        : "+f"(d[0]), "+f"(d[1]), "+f"(d[2]), "+f"(d[3])
        : "r"(a[0]), "r"(a[1]), "r"(a[2]), "r"(a[3]), "r"(b[0]), "r"(b[1]));
}

// ---------------------------------------------------------------------------
// Row L2-normalize -> scaled fp16. which=0: xh+xl split; which=1: yh single.
// ---------------------------------------------------------------------------
__global__ void __launch_bounds__(256) normalize_rows(const float* __restrict__ in, int which) {
    int row = blockIdx.x;
    const float4* src = (const float4*)(in + (size_t)row * Dd);
    float4 val = src[threadIdx.x];
    float ss = val.x * val.x + val.y * val.y + val.z * val.z + val.w * val.w;
#pragma unroll
    for (int o = 16; o; o >>= 1) ss += __shfl_xor_sync(0xffffffffu, ss, o);
    __shared__ float wsum[8];
    int lane = threadIdx.x & 31, warp = threadIdx.x >> 5;
    if (!lane) wsum[warp] = ss;
    __syncthreads();
    float tot = 0.f;
#pragma unroll
    for (int p = 0; p < 8; p++) tot += wsum[p];
    float inv = rsqrtf(tot) * 32.0f;   // scale by 32 to keep fp16 residuals normal
    float o4[4] = {val.x * inv, val.y * inv, val.z * inv, val.w * inv};
    size_t off = (size_t)row * Dd + threadIdx.x * 4;
    if (which) {
        __half h[4];
#pragma unroll
        for (int c = 0; c < 4; c++) h[c] = __float2half(o4[c]);
        *(uint2*)&g_yh[off] = *(uint2*)h;
    } else {
        __half h[4], l[4];
#pragma unroll
        for (int c = 0; c < 4; c++) {
            h[c] = __float2half(o4[c]);
            l[c] = __float2half(o4[c] - __half2float(h[c]));
        }
        *(uint2*)&g_xh[off] = *(uint2*)h;
        *(uint2*)&g_xl[off] = *(uint2*)l;
    }
}

// ---------------------------------------------------------------------------
// Transpose X -> Xt single fp16 (unscaled), [4096,1024] -> [1024,4096]
// ---------------------------------------------------------------------------
__global__ void __launch_bounds__(256) transpose_X(const float* __restrict__ X) {
    __shared__ float s[32][33];
    int j0 = blockIdx.x * 32;
    int i0 = blockIdx.y * 32;
    int tx = threadIdx.x & 31, ty = threadIdx.x >> 5;
#pragma unroll
    for (int r = 0; r < 4; r++)
        s[ty + r * 8][tx] = X[(size_t)(i0 + ty + r * 8) * Dd + j0 + tx];
    __syncthreads();
#pragma unroll
    for (int r = 0; r < 4; r++) {
        int orow = j0 + ty + r * 8;
        g_Xth[(size_t)orow * Nn + i0 + tx] = __float2half(s[tx][ty + r * 8]);
    }
}

// ---------------------------------------------------------------------------
// mma.sync fp16 2-term GEMM, 128x128 tile, BK=64, 3-stage cp.async pipeline.
// D = (Ah+Al) . Bh^T, epilogue scale.
// mode 0: -> g_A (fp32, x2^-10) + g_K16 (bf16 exp)
// mode 1: -> Cout (x2^-26, ld=Dd)
// ---------------------------------------------------------------------------
#define TILE_B 16384
#define STAGE_B (3 * TILE_B)
#define GEMM_SMEM (3 * STAGE_B)

__device__ __forceinline__ void load_stage(
    const __half* __restrict__ Ah, const __half* __restrict__ Al,
    const __half* __restrict__ Bh,
    int ldA, int ldB, int rowA, int rowB, int k0, uint32_t sb, int tid)
{
#pragma unroll
    for (int it = 0; it < 4; it++) {
        int i = tid + it * 256;
        int r = i >> 3, c = i & 7;
        uint32_t off = (uint32_t)((r << 7) | (c << 4));
        uint32_t sw = off ^ ((uint32_t)(r & 7) << 4);
        size_t ga = (size_t)(rowA + r) * ldA + k0 + c * 8;
        size_t gb = (size_t)(rowB + r) * ldB + k0 + c * 8;
        cp16(sb + sw,              Ah + ga);
        cp16(sb + TILE_B + sw,     Al + ga);
        cp16(sb + 2 * TILE_B + sw, Bh + gb);
    }
}

__global__ void __launch_bounds__(256) gemm_fp16x2(int mode, float* __restrict__ Cout) {
    extern __shared__ char smem[];
    uint32_t sbase = smem_u32(smem);
    int tid = threadIdx.x;
    int lane = tid & 31, wid = tid >> 5;
    int wm = wid >> 2, wn = wid & 3;      // 2 x 4 warps -> warp tile 64 x 32

    const __half *Ah, *Al, *Bh;
    int K, ldA, ldB;
    if (mode == 0) { Ah = g_xh;  Al = g_xl;  Bh = g_yh;  K = Dd; ldA = Dd; ldB = Dd; }
    else           { Ah = g_Tth; Al = g_Ttl; Bh = g_Xth; K = Nn; ldA = Nn; ldB = Nn; }

    int bm = blockIdx.y, bn = blockIdx.x;
    int rowA = bm * 128, rowB = bn * 128;

    float acc[4][4][4];
#pragma unroll
    for (int a = 0; a < 4; a++)
#pragma unroll
        for (int b = 0; b < 4; b++)
#pragma unroll
            for (int c = 0; c < 4; c++) acc[a][b][c] = 0.f;

    // A fragment addressing
    int arow = wm * 64 + (lane & 7) + 8 * ((lane >> 3) & 1);
    uint32_t akb = 16u * (lane >> 4);
    uint32_t xorA = (uint32_t)(arow & 7) << 4;
    uint32_t aRB = (uint32_t)arow << 7;
    // B fragment addressing: x4 covers two n8 tiles (16 rows)
    int browl = (lane & 7) + 8 * (lane >> 4);
    uint32_t bkb = 16u * ((lane >> 3) & 1);
    uint32_t xorB = (uint32_t)(lane & 7) << 4;

    const int NT = K / 64;

    load_stage(Ah, Al, Bh, ldA, ldB, rowA, rowB, 0, sbase, tid);
    CP_COMMIT();
    load_stage(Ah, Al, Bh, ldA, ldB, rowA, rowB, 64, sbase + STAGE_B, tid);
    CP_COMMIT();

    for (int kt = 0; kt < NT; kt++) {
        if (kt + 2 < NT) { CP_WAIT(1); } else { CP_WAIT(0); }
        __syncthreads();
        if (kt + 2 < NT) {
            load_stage(Ah, Al, Bh, ldA, ldB, rowA, rowB, (kt + 2) * 64,
                       sbase + (uint32_t)((kt + 2) % 3) * STAGE_B, tid);
            CP_COMMIT();
        }
        uint32_t sb = sbase + (uint32_t)(kt % 3) * STAGE_B;
        uint32_t sAh = sb, sAl = sb + TILE_B, sBh = sb + 2 * TILE_B;
#pragma unroll
        for (int ks = 0; ks < 4; ks++) {
            uint32_t ca = (akb + 32u * ks) ^ xorA;
            uint32_t cb = (bkb + 32u * ks) ^ xorB;
            uint32_t fAh[4][4], fAl[4][4], fBh[2][4];
#pragma unroll
            for (int mt = 0; mt < 4; mt++) {
                uint32_t ao = aRB + (uint32_t)mt * 2048 + ca;
                ldsm_x4(fAh[mt], sAh + ao);
                ldsm_x4(fAl[mt], sAl + ao);
            }
#pragma unroll
            for (int nt2 = 0; nt2 < 2; nt2++) {
                uint32_t bo = ((uint32_t)(wn * 32 + nt2 * 16 + browl) << 7) + cb;
                ldsm_x4(fBh[nt2], sBh + bo);
            }
#pragma unroll
            for (int nt2 = 0; nt2 < 2; nt2++)
#pragma unroll
                for (int mt = 0; mt < 4; mt++) {
                    mma_fp16(acc[mt][2 * nt2],     fAh[mt], &fBh[nt2][0]);
                    mma_fp16(acc[mt][2 * nt2],     fAl[mt], &fBh[nt2][0]);
                    mma_fp16(acc[mt][2 * nt2 + 1], fAh[mt], &fBh[nt2][2]);
                    mma_fp16(acc[mt][2 * nt2 + 1], fAl[mt], &fBh[nt2][2]);
                }
        }
    }

    int r0 = bm * 128 + wm * 64 + (lane >> 2);
    int c0 = bn * 128 + wn * 32 + (lane & 3) * 2;
    if (mode == 0) {
#pragma unroll
        for (int mt = 0; mt < 4; mt++)
#pragma unroll
            for (int half = 0; half < 2; half++) {
                int row = r0 + mt * 16 + half * 8;
                size_t base = (size_t)row * Mm;
#pragma unroll
                for (int nt = 0; nt < 4; nt++) {
                    float d0 = acc[mt][nt][half * 2 + 0] * EPI1;
                    float d1 = acc[mt][nt][half * 2 + 1] * EPI1;
                    int col = c0 + nt * 8;
                    *(float2*)&g_A[base + col] = make_float2(d0, d1);
                    __nv_bfloat162 kp = __floats2bfloat162_rn(expf(d0), expf(d1));
                    *(__nv_bfloat162*)&g_K16[base + col] = kp;
                }
            }
    } else {
#pragma unroll
        for (int mt = 0; mt < 4; mt++)
#pragma unroll
            for (int half = 0; half < 2; half++) {
                int row = r0 + mt * 16 + half * 8;
                size_t base = (size_t)row * Dd;
#pragma unroll
                for (int nt = 0; nt < 4; nt++) {
                    int col = c0 + nt * 8;
                    *(float2*)&Cout[base + col] =
                        make_float2(acc[mt][nt][half * 2 + 0] * TSCALE_INV,
                                    acc[mt][nt][half * 2 + 1] * TSCALE_INV);
                }
            }
    }
}

// ---------------------------------------------------------------------------
// Sinkhorn: fused iteration (bf16 K, fp32 accumulate).
// ---------------------------------------------------------------------------
__global__ void init_uv() {
    int i = blockIdx.x * 256 + threadIdx.x;
    g_u[i] = 1.0f / Nn;
    g_v[i] = 1.0f / Mm;
}

__global__ void __launch_bounds__(256) sink_iter() {
    __shared__ float ush[ROWS_PB];
    int tid = threadIdx.x;
    int warp = tid >> 5, lane = tid & 31;
    int row0 = blockIdx.x * ROWS_PB;

#pragma unroll
    for (int rr = 0; rr < 4; rr++) {
        int rl = warp * 4 + rr;
        const uint4* Kr = (const uint4*)(g_K16 + (size_t)(row0 + rl) * Mm);
        const float4* v4 = (const float4*)g_v;
        float acc = 0.f;
#pragma unroll 4
        for (int j = lane; j < Mm / 8; j += 32) {
            uint4 kq = Kr[j];
            float4 va = v4[2 * j], vb = v4[2 * j + 1];
            float2 k0 = __bfloat1622float2(*(__nv_bfloat162*)&kq.x);
            float2 k1 = __bfloat1622float2(*(__nv_bfloat162*)&kq.y);
            float2 k2 = __bfloat1622float2(*(__nv_bfloat162*)&kq.z);
            float2 k3 = __bfloat1622float2(*(__nv_bfloat162*)&kq.w);
            acc += k0.x * va.x + k0.y * va.y + k1.x * va.z + k1.y * va.w
                 + k2.x * vb.x + k2.y * vb.y + k3.x * vb.z + k3.y * vb.w;
        }
#pragma unroll
        for (int o = 16; o; o >>= 1) acc += __shfl_xor_sync(0xffffffffu, acc, o);
        if (!lane) {
            float u = sqrtf((1.0f / Nn) / acc);
            ush[rl] = u;
            g_u[row0 + rl] = u;
        }
    }
    __syncthreads();

#pragma unroll
    for (int t = 0; t < 8; t++) {
        int j = tid * 2 + t * 512;
        float ax = 0.f, ay = 0.f;
#pragma unroll 8
        for (int i = 0; i < ROWS_PB; i++) {
            __nv_bfloat162 kk = *(const __nv_bfloat162*)(g_K16 + (size_t)(row0 + i) * Mm + j);
            float2 kf = __bfloat1622float2(kk);
            float u = ush[i];
            ax += kf.x * u;
            ay += kf.y * u;
        }
        *(float2*)&g_part[(size_t)blockIdx.x * Mm + j] = make_float2(ax, ay);
    }
}

__global__ void __launch_bounds__(256) sink_vfin() {
    int j = blockIdx.x * 256 + threadIdx.x;
    float s = 0.f;
#pragma unroll 8
    for (int b = 0; b < NBLK; b++) s += g_part[(size_t)b * Mm + j];
    g_v[j] = sqrtf((1.0f / Mm) / s);
}

// ---------------------------------------------------------------------------
// finalize: T = A*u*exp(A)*v (fp32 -> d_out), plus Tt hi/lo fp16 (x2^26)
// ---------------------------------------------------------------------------
__global__ void __launch_bounds__(256) finalize_T(float* __restrict__ T) {
    __shared__ float s[32][33];
    int j0 = blockIdx.x * 32, i0 = blockIdx.y * 32;
    int tx = threadIdx.x & 31, ty = threadIdx.x >> 5;
    float vj = g_v[j0 + tx];
#pragma unroll
    for (int r = 0; r < 4; r++) {
        int row = i0 + ty + r * 8;
        float a = g_A[(size_t)row * Mm + j0 + tx];
        float t = a * g_u[row] * expf(a) * vj;
        T[(size_t)row * Mm + j0 + tx] = t;
        s[ty + r * 8][tx] = t;
    }
    __syncthreads();
#pragma unroll
    for (int r = 0; r < 4; r++) {
        int orow = j0 + ty + r * 8;
        float ts = s[tx][ty + r * 8] * TSCALE;
        __half h = __float2half(ts);
        __half l = __float2half(ts - __half2float(h));
        g_Tth[(size_t)orow * Nn + i0 + tx] = h;
        g_Ttl[(size_t)orow * Nn + i0 + tx] = l;
    }
}

// ---------------------------------------------------------------------------
extern "C" void kernel_launch(void* const* d_in, const int* in_sizes, int n_in,
                              void* d_out, int out_size) {
    const float* X = (const float*)d_in[0];
    const float* Y = (const float*)d_in[1];
    float* out = (float*)d_out;
    float* aligned = out;                          // [4096,1024]
    float* Tmat = out + (size_t)Mm * Dd;           // [4096,4096]

    cudaFuncSetAttribute(gemm_fp16x2, cudaFuncAttributeMaxDynamicSharedMemorySize, GEMM_SMEM);

    normalize_rows<<<Nn, 256>>>(X, 0);
    normalize_rows<<<Mm, 256>>>(Y, 1);
    transpose_X<<<dim3(Dd / 32, Nn / 32), 256>>>(X);

    gemm_fp16x2<<<dim3(Mm / 128, Nn / 128), 256, GEMM_SMEM>>>(0, nullptr);

    init_uv<<<Nn / 256, 256>>>();
    for (int it = 0; it < NITER; it++) {
        sink_iter<<<NBLK, 256>>>();
        sink_vfin<<<Mm / 256, 256>>>();
    }

    finalize_T<<<dim3(Mm / 32, Nn / 32), 256>>>(Tmat);

    gemm_fp16x2<<<dim3(Dd / 128, Mm / 128), 256, GEMM_SMEM>>>(1, aligned);
}

// round 7
// speedup vs baseline: 17.4598x; 1.4927x over previous
#include <cuda_runtime.h>
#include <cuda_bf16.h>
#include <cuda_fp16.h>
#include <math.h>
#include <stdint.h>

#define Nn 4096
#define Mm 4096
#define Dd 1024
#define NITER 10
#define ROWS_PB 32
#define NBLK (Nn / ROWS_PB)   // 128

#define TSCALE 67108864.0f                  // 2^26
#define TSCALE_INV 1.4901161193847656e-8f   // 2^-26
#define EPI1 0.0009765625f                  // 2^-10 (both operands scaled by 32)

// ---------------------------------------------------------------------------
// Static device scratch (no runtime allocation allowed).
// ---------------------------------------------------------------------------
static __device__ __half g_xh[(size_t)Nn * Dd];
static __device__ __half g_xl[(size_t)Nn * Dd];
static __device__ __half g_yh[(size_t)Mm * Dd];
static __device__ float  g_A[(size_t)Nn * Mm];
static __device__ __nv_bfloat16 g_K16[(size_t)Nn * Mm];
static __device__ __half g_Tth[(size_t)Mm * Nn];
static __device__ __half g_Xth[(size_t)Dd * Nn];
static __device__ float g_u[Nn];
static __device__ float g_v[Mm];
static __device__ float g_part[(size_t)NBLK * Mm];

// ---------------------------------------------------------------------------
// PTX helpers (baseline, non-arch-gated)
// ---------------------------------------------------------------------------
__device__ __forceinline__ uint32_t smem_u32(const void* p) {
    uint32_t a;
    asm("{ .reg .u64 t; cvta.to.shared.u64 t, %1; cvt.u32.u64 %0, t; }"
        : "=r"(a) : "l"(p));
    return a;
}
__device__ __forceinline__ void cp16(uint32_t saddr, const void* g) {
    asm volatile("cp.async.cg.shared.global [%0], [%1], 16;" :: "r"(saddr), "l"(g) : "memory");
}
#define CP_COMMIT() asm volatile("cp.async.commit_group;" ::: "memory")
#define CP_WAIT(n)  asm volatile("cp.async.wait_group %0;" :: "n"(n) : "memory")

__device__ __forceinline__ void ldsm_x4(uint32_t* r, uint32_t addr) {
    asm volatile("ldmatrix.sync.aligned.m8n8.x4.shared.b16 {%0,%1,%2,%3}, [%4];"
        : "=r"(r[0]), "=r"(r[1]), "=r"(r[2]), "=r"(r[3]) : "r"(addr));
}
__device__ __forceinline__ void mma_fp16(float* d, const uint32_t* a, const uint32_t* b) {
    asm volatile("mma.sync.aligned.m16n8k16.row.col.f32.f16.f16.f32 "
        "{%0,%1,%2,%3}, {%4,%5,%6,%7}, {%8,%9}, {%0,%1,%2,%3};"
        : "+f"(d[0]), "+f"(d[1]), "+f"(d[2]), "+f"(d[3])
        : "r"(a[0]), "r"(a[1]), "r"(a[2]), "r"(a[3]), "r"(b[0]), "r"(b[1]));
}

// ---------------------------------------------------------------------------
// Row L2-normalize -> scaled fp16. which=0: xh+xl split; which=1: yh single.
// ---------------------------------------------------------------------------
__global__ void __launch_bounds__(256) normalize_rows(const float* __restrict__ in, int which) {
    int row = blockIdx.x;
    const float4* src = (const float4*)(in + (size_t)row * Dd);
    float4 val = src[threadIdx.x];
    float ss = val.x * val.x + val.y * val.y + val.z * val.z + val.w * val.w;
#pragma unroll
    for (int o = 16; o; o >>= 1) ss += __shfl_xor_sync(0xffffffffu, ss, o);
    __shared__ float wsum[8];
    int lane = threadIdx.x & 31, warp = threadIdx.x >> 5;
    if (!lane) wsum[warp] = ss;
    __syncthreads();
    float tot = 0.f;
#pragma unroll
    for (int p = 0; p < 8; p++) tot += wsum[p];
    float inv = rsqrtf(tot) * 32.0f;
    float o4[4] = {val.x * inv, val.y * inv, val.z * inv, val.w * inv};
    size_t off = (size_t)row * Dd + threadIdx.x * 4;
    if (which) {
        __half h[4];
#pragma unroll
        for (int c = 0; c < 4; c++) h[c] = __float2half(o4[c]);
        *(uint2*)&g_yh[off] = *(uint2*)h;
    } else {
        __half h[4], l[4];
#pragma unroll
        for (int c = 0; c < 4; c++) {
            h[c] = __float2half(o4[c]);
            l[c] = __float2half(o4[c] - __half2float(h[c]));
        }
        *(uint2*)&g_xh[off] = *(uint2*)h;
        *(uint2*)&g_xl[off] = *(uint2*)l;
    }
}

// ---------------------------------------------------------------------------
// Transpose X -> Xt single fp16 (unscaled), [4096,1024] -> [1024,4096]
// ---------------------------------------------------------------------------
__global__ void __launch_bounds__(256) transpose_X(const float* __restrict__ X) {
    __shared__ float s[32][33];
    int j0 = blockIdx.x * 32;
    int i0 = blockIdx.y * 32;
    int tx = threadIdx.x & 31, ty = threadIdx.x >> 5;
#pragma unroll
    for (int r = 0; r < 4; r++)
        s[ty + r * 8][tx] = X[(size_t)(i0 + ty + r * 8) * Dd + j0 + tx];
    __syncthreads();
#pragma unroll
    for (int r = 0; r < 4; r++) {
        int orow = j0 + ty + r * 8;
        g_Xth[(size_t)orow * Nn + i0 + tx] = __float2half(s[tx][ty + r * 8]);
    }
}

// ---------------------------------------------------------------------------
// mma.sync GEMM, CTA tile 128x256, warp tile 64x64, BK=64, 3-stage cp.async.
// MODE 0: D = (xh+xl) . yh^T -> g_A (fp32 x2^-10) + g_K16 (bf16 exp)
// MODE 1: D = Tth . Xth^T    -> Cout (x2^-26, ld=Dd)
// SMEM stage: [Ah 16K][Al 16K][B 32K] = 64K; 3 stages = 192K.
// ---------------------------------------------------------------------------
#define TILE_A 16384
#define STAGE_B6 65536
#define GEMM_SMEM (3 * STAGE_B6)

template <int MODE>
__device__ __forceinline__ void load_stage(
    const __half* __restrict__ Ah, const __half* __restrict__ Al,
    const __half* __restrict__ Bh,
    int ldA, int ldB, int rowA, int rowB, int k0, uint32_t sb, int tid)
{
#pragma unroll
    for (int it = 0; it < 4; it++) {
        int i = tid + it * 256;
        int r = i >> 3, c = i & 7;
        uint32_t off = (uint32_t)((r << 7) | (c << 4));
        uint32_t sw = off ^ ((uint32_t)(r & 7) << 4);
        size_t ga = (size_t)(rowA + r) * ldA + k0 + c * 8;
        cp16(sb + sw, Ah + ga);
        if (MODE == 0) cp16(sb + TILE_A + sw, Al + ga);
    }
#pragma unroll
    for (int it = 0; it < 8; it++) {
        int i = tid + it * 256;
        int r = i >> 3, c = i & 7;
        uint32_t off = (uint32_t)((r << 7) | (c << 4));
        uint32_t sw = off ^ ((uint32_t)(r & 7) << 4);
        size_t gb = (size_t)(rowB + r) * ldB + k0 + c * 8;
        cp16(sb + 2 * TILE_A + sw, Bh + gb);
    }
}

template <int MODE>
__global__ void __launch_bounds__(256) gemm_wide(float* __restrict__ Cout) {
    extern __shared__ char smem[];
    uint32_t sbase = smem_u32(smem);
    int tid = threadIdx.x;
    int lane = tid & 31, wid = tid >> 5;
    int wm = wid >> 2, wn = wid & 3;      // 2 x 4 warps -> warp tile 64 x 64

    const __half *Ah, *Al, *Bh;
    int K, ldA, ldB;
    if (MODE == 0) { Ah = g_xh;  Al = g_xl; Bh = g_yh;  K = Dd; ldA = Dd; ldB = Dd; }
    else           { Ah = g_Tth; Al = 0;    Bh = g_Xth; K = Nn; ldA = Nn; ldB = Nn; }

    int bm = blockIdx.y, bn = blockIdx.x;
    int rowA = bm * 128, rowB = bn * 256;

    float acc[4][8][4];
#pragma unroll
    for (int a = 0; a < 4; a++)
#pragma unroll
        for (int b = 0; b < 8; b++)
#pragma unroll
            for (int c = 0; c < 4; c++) acc[a][b][c] = 0.f;

    // A fragment addressing
    int arow = wm * 64 + (lane & 7) + 8 * ((lane >> 3) & 1);
    uint32_t akb = 16u * (lane >> 4);
    uint32_t xorA = (uint32_t)(arow & 7) << 4;
    uint32_t aRB = (uint32_t)arow << 7;
    // B fragment addressing: x4 covers two n8 tiles (16 rows)
    int browl = (lane & 7) + 8 * (lane >> 4);
    uint32_t bkb = 16u * ((lane >> 3) & 1);
    uint32_t xorB = (uint32_t)(lane & 7) << 4;

    const int NT = K / 64;

    load_stage<MODE>(Ah, Al, Bh, ldA, ldB, rowA, rowB, 0, sbase, tid);
    CP_COMMIT();
    load_stage<MODE>(Ah, Al, Bh, ldA, ldB, rowA, rowB, 64, sbase + STAGE_B6, tid);
    CP_COMMIT();

    for (int kt = 0; kt < NT; kt++) {
        if (kt + 2 < NT) { CP_WAIT(1); } else { CP_WAIT(0); }
        __syncthreads();
        if (kt + 2 < NT) {
            load_stage<MODE>(Ah, Al, Bh, ldA, ldB, rowA, rowB, (kt + 2) * 64,
                             sbase + (uint32_t)((kt + 2) % 3) * STAGE_B6, tid);
            CP_COMMIT();
        }
        uint32_t sb = sbase + (uint32_t)(kt % 3) * STAGE_B6;
        uint32_t sAh = sb, sAl = sb + TILE_A, sBh = sb + 2 * TILE_A;
#pragma unroll
        for (int ks = 0; ks < 4; ks++) {
            uint32_t ca = (akb + 32u * ks) ^ xorA;
            uint32_t cb = (bkb + 32u * ks) ^ xorB;
            uint32_t fAh[4][4], fAl[4][4], fB[4][4];
#pragma unroll
            for (int mt = 0; mt < 4; mt++) {
                uint32_t ao = aRB + (uint32_t)mt * 2048 + ca;
                ldsm_x4(fAh[mt], sAh + ao);
                if (MODE == 0) ldsm_x4(fAl[mt], sAl + ao);
            }
#pragma unroll
            for (int nt2 = 0; nt2 < 4; nt2++) {
                uint32_t bo = ((uint32_t)(wn * 64 + nt2 * 16 + browl) << 7) + cb;
                ldsm_x4(fB[nt2], sBh + bo);
            }
#pragma unroll
            for (int nt2 = 0; nt2 < 4; nt2++)
#pragma unroll
                for (int mt = 0; mt < 4; mt++) {
                    mma_fp16(acc[mt][2 * nt2],     fAh[mt], &fB[nt2][0]);
                    mma_fp16(acc[mt][2 * nt2 + 1], fAh[mt], &fB[nt2][2]);
                    if (MODE == 0) {
                        mma_fp16(acc[mt][2 * nt2],     fAl[mt], &fB[nt2][0]);
                        mma_fp16(acc[mt][2 * nt2 + 1], fAl[mt], &fB[nt2][2]);
                    }
                }
        }
    }

    int r0 = bm * 128 + wm * 64 + (lane >> 2);
    int c0 = bn * 256 + wn * 64 + (lane & 3) * 2;
#pragma unroll
    for (int mt = 0; mt < 4; mt++)
#pragma unroll
        for (int half = 0; half < 2; half++) {
            int row = r0 + mt * 16 + half * 8;
            if (MODE == 0) {
                size_t base = (size_t)row * Mm;
#pragma unroll
                for (int nt = 0; nt < 8; nt++) {
                    float d0 = acc[mt][nt][half * 2 + 0] * EPI1;
                    float d1 = acc[mt][nt][half * 2 + 1] * EPI1;
                    int col = c0 + nt * 8;
                    *(float2*)&g_A[base + col] = make_float2(d0, d1);
                    __nv_bfloat162 kp = __floats2bfloat162_rn(expf(d0), expf(d1));
                    *(__nv_bfloat162*)&g_K16[base + col] = kp;
                }
            } else {
                size_t base = (size_t)row * Dd;
#pragma unroll
                for (int nt = 0; nt < 8; nt++) {
                    int col = c0 + nt * 8;
                    *(float2*)&Cout[base + col] =
                        make_float2(acc[mt][nt][half * 2 + 0] * TSCALE_INV,
                                    acc[mt][nt][half * 2 + 1] * TSCALE_INV);
                }
            }
        }
}

// ---------------------------------------------------------------------------
// Sinkhorn: fused iteration (bf16 K, fp32 accumulate), 512 threads/block.
// ---------------------------------------------------------------------------
__global__ void init_uv() {
    int i = blockIdx.x * 256 + threadIdx.x;
    g_u[i] = 1.0f / Nn;
    g_v[i] = 1.0f / Mm;
}

__global__ void __launch_bounds__(512) sink_iter() {
    __shared__ float ush[ROWS_PB];
    int tid = threadIdx.x;
    int warp = tid >> 5, lane = tid & 31;   // 16 warps
    int row0 = blockIdx.x * ROWS_PB;

    // Phase 1: each warp handles 2 rows
#pragma unroll
    for (int rr = 0; rr < 2; rr++) {
        int rl = warp * 2 + rr;
        const uint4* Kr = (const uint4*)(g_K16 + (size_t)(row0 + rl) * Mm);
        const float4* v4 = (const float4*)g_v;
        float acc = 0.f;
#pragma unroll 4
        for (int j = lane; j < Mm / 8; j += 32) {
            uint4 kq = Kr[j];
            float4 va = v4[2 * j], vb = v4[2 * j + 1];
            float2 k0 = __bfloat1622float2(*(__nv_bfloat162*)&kq.x);
            float2 k1 = __bfloat1622float2(*(__nv_bfloat162*)&kq.y);
            float2 k2 = __bfloat1622float2(*(__nv_bfloat162*)&kq.z);
            float2 k3 = __bfloat1622float2(*(__nv_bfloat162*)&kq.w);
            acc += k0.x * va.x + k0.y * va.y + k1.x * va.z + k1.y * va.w
                 + k2.x * vb.x + k2.y * vb.y + k3.x * vb.z + k3.y * vb.w;
        }
#pragma unroll
        for (int o = 16; o; o >>= 1) acc += __shfl_xor_sync(0xffffffffu, acc, o);
        if (!lane) {
            float u = sqrtf((1.0f / Nn) / acc);
            ush[rl] = u;
            g_u[row0 + rl] = u;
        }
    }
    __syncthreads();

    // Phase 2: column partials over this block's 32-row slice
#pragma unroll
    for (int t = 0; t < 4; t++) {
        int j = tid * 2 + t * 1024;
        float ax = 0.f, ay = 0.f;
#pragma unroll 8
        for (int i = 0; i < ROWS_PB; i++) {
            __nv_bfloat162 kk = *(const __nv_bfloat162*)(g_K16 + (size_t)(row0 + i) * Mm + j);
            float2 kf = __bfloat1622float2(kk);
            float u = ush[i];
            ax += kf.x * u;
            ay += kf.y * u;
        }
        *(float2*)&g_part[(size_t)blockIdx.x * Mm + j] = make_float2(ax, ay);
    }
}

__global__ void __launch_bounds__(256) sink_vfin() {
    int j = blockIdx.x * 256 + threadIdx.x;
    float s = 0.f;
#pragma unroll 8
    for (int b = 0; b < NBLK; b++) s += g_part[(size_t)b * Mm + j];
    g_v[j] = sqrtf((1.0f / Mm) / s);
}

// ---------------------------------------------------------------------------
// finalize: T = A*u*exp(A)*v (fp32 -> d_out), plus Tt fp16 (x2^26, transposed)
// ---------------------------------------------------------------------------
__global__ void __launch_bounds__(256) finalize_T(float* __restrict__ T) {
    __shared__ float s[32][33];
    int j0 = blockIdx.x * 32, i0 = blockIdx.y * 32;
    int tx = threadIdx.x & 31, ty = threadIdx.x >> 5;
    float vj = g_v[j0 + tx];
#pragma unroll
    for (int r = 0; r < 4; r++) {
        int row = i0 + ty + r * 8;
        float a = g_A[(size_t)row * Mm + j0 + tx];
        float t = a * g_u[row] * expf(a) * vj;
        T[(size_t)row * Mm + j0 + tx] = t;
        s[ty + r * 8][tx] = t;
    }
    __syncthreads();
#pragma unroll
    for (int r = 0; r < 4; r++) {
        int orow = j0 + ty + r * 8;
        g_Tth[(size_t)orow * Nn + i0 + tx] = __float2half(s[tx][ty + r * 8] * TSCALE);
    }
}

// ---------------------------------------------------------------------------
extern "C" void kernel_launch(void* const* d_in, const int* in_sizes, int n_in,
                              void* d_out, int out_size) {
    const float* X = (const float*)d_in[0];
    const float* Y = (const float*)d_in[1];
    float* out = (float*)d_out;
    float* aligned = out;                          // [4096,1024]
    float* Tmat = out + (size_t)Mm * Dd;           // [4096,4096]

    cudaFuncSetAttribute(gemm_wide<0>, cudaFuncAttributeMaxDynamicSharedMemorySize, GEMM_SMEM);
    cudaFuncSetAttribute(gemm_wide<1>, cudaFuncAttributeMaxDynamicSharedMemorySize, GEMM_SMEM);

    normalize_rows<<<Nn, 256>>>(X, 0);
    normalize_rows<<<Mm, 256>>>(Y, 1);
    transpose_X<<<dim3(Dd / 32, Nn / 32), 256>>>(X);

    gemm_wide<0><<<dim3(Mm / 256, Nn / 128), 256, GEMM_SMEM>>>(nullptr);

    init_uv<<<Nn / 256, 256>>>();
    for (int it = 0; it < NITER; it++) {
        sink_iter<<<NBLK, 512>>>();
        sink_vfin<<<Mm / 256, 256>>>();
    }

    finalize_T<<<dim3(Mm / 32, Nn / 32), 256>>>(Tmat);

    gemm_wide<1><<<dim3(Dd / 256, Mm / 128), 256, GEMM_SMEM>>>(aligned);
}